// round 1
// baseline (speedup 1.0000x reference)
#include <cuda_runtime.h>
#include <stdint.h>

#define Uc   512
#define Bc   16
#define Dc   512
#define Hc   8
#define Rc   32
#define Sc   16
#define Mc   32
#define HDc  64
#define Qc   560
#define KVc  576
#define PEc  1023
#define BHc  128
#define RUc  544
#define SCALE_F 0.125f
#define NEG_INF_F -100000000.0f

// ---------------- scratch (device globals; no allocation allowed) ----------
__device__ float g_qin[Qc * Bc * Dc];        // concat(rc, utt, summary)
__device__ float g_kvin[KVc * Bc * Dc];      // concat(memory, rc, utt)
__device__ float g_query[Qc * Bc * Dc];      // q projection
__device__ float g_pos[PEc * Dc];            // pos_emb @ Wpos^T
__device__ float g_w[(size_t)BHc * Qc * KVc];// scores -> probs
__device__ float g_attn[Qc * Bc * Dc];       // attention output (Q,B,D)

// ---------------- gathers ---------------------------------------------------
__global__ void gather_qin(const float* __restrict__ rc,
                           const float* __restrict__ utt,
                           const float* __restrict__ summ) {
    int idx = blockIdx.x * blockDim.x + threadIdx.x;
    if (idx >= Qc * Bc * Dc) return;
    int q = idx / (Bc * Dc);
    int rem = idx - q * (Bc * Dc);
    float v;
    if (q < Rc)            v = rc[q * Bc * Dc + rem];
    else if (q < Rc + Uc)  v = utt[(q - Rc) * Bc * Dc + rem];
    else                   v = summ[(q - Rc - Uc) * Bc * Dc + rem];
    g_qin[idx] = v;
}

__global__ void gather_kvin(const float* __restrict__ mem,
                            const float* __restrict__ rc,
                            const float* __restrict__ utt) {
    int idx = blockIdx.x * blockDim.x + threadIdx.x;
    if (idx >= KVc * Bc * Dc) return;
    int q = idx / (Bc * Dc);
    int rem = idx - q * (Bc * Dc);
    float v;
    if (q < Mc)            v = mem[q * Bc * Dc + rem];
    else if (q < Mc + Rc)  v = rc[(q - Mc) * Bc * Dc + rem];
    else                   v = utt[(q - Mc - Rc) * Bc * Dc + rem];
    g_kvin[idx] = v;
}

// ---------------- generic NT SGEMM: C = A(rows,K) @ W(N,K)^T + bias ---------
// mode 0: out1[row*N+col]
// mode 1: kv split  (N=1024): col<512 -> out1[row*512+col], else out2
// mode 2: final split+clip: rows=(q*B+b); q<RU -> out1; else clip -> out2
__global__ void sgemm_nt(const float* __restrict__ A,
                         const float* __restrict__ W,
                         const float* __restrict__ bias,
                         int rows, int N, int K,
                         float* __restrict__ out1,
                         float* __restrict__ out2,
                         int mode) {
    __shared__ float As[16][68];
    __shared__ float Bs[16][68];
    int tx = threadIdx.x, ty = threadIdx.y;
    int t  = ty * 16 + tx;
    int lr = t >> 2;           // 0..63
    int lk = (t & 3) << 2;     // 0,4,8,12
    int rowBase = blockIdx.y * 64;
    int colBase = blockIdx.x * 64;

    float acc[4][4];
#pragma unroll
    for (int i = 0; i < 4; i++)
#pragma unroll
        for (int j = 0; j < 4; j++) acc[i][j] = 0.f;

    for (int k0 = 0; k0 < K; k0 += 16) {
        int grow = rowBase + lr;
        float4 av = make_float4(0.f, 0.f, 0.f, 0.f);
        if (grow < rows)
            av = *(const float4*)(A + (size_t)grow * K + k0 + lk);
        As[lk + 0][lr] = av.x; As[lk + 1][lr] = av.y;
        As[lk + 2][lr] = av.z; As[lk + 3][lr] = av.w;

        float4 wv = *(const float4*)(W + (size_t)(colBase + lr) * K + k0 + lk);
        Bs[lk + 0][lr] = wv.x; Bs[lk + 1][lr] = wv.y;
        Bs[lk + 2][lr] = wv.z; Bs[lk + 3][lr] = wv.w;
        __syncthreads();

#pragma unroll
        for (int kk = 0; kk < 16; kk++) {
            float4 a = *(const float4*)&As[kk][ty * 4];
            float4 b = *(const float4*)&Bs[kk][tx * 4];
            acc[0][0] += a.x * b.x; acc[0][1] += a.x * b.y; acc[0][2] += a.x * b.z; acc[0][3] += a.x * b.w;
            acc[1][0] += a.y * b.x; acc[1][1] += a.y * b.y; acc[1][2] += a.y * b.z; acc[1][3] += a.y * b.w;
            acc[2][0] += a.z * b.x; acc[2][1] += a.z * b.y; acc[2][2] += a.z * b.z; acc[2][3] += a.z * b.w;
            acc[3][0] += a.w * b.x; acc[3][1] += a.w * b.y; acc[3][2] += a.w * b.z; acc[3][3] += a.w * b.w;
        }
        __syncthreads();
    }

    float bj[4];
#pragma unroll
    for (int j = 0; j < 4; j++) {
        int col = colBase + tx * 4 + j;
        bj[j] = bias ? bias[col] : 0.f;
    }
#pragma unroll
    for (int i = 0; i < 4; i++) {
        int grow = rowBase + ty * 4 + i;
        if (grow >= rows) continue;
#pragma unroll
        for (int j = 0; j < 4; j++) {
            int col = colBase + tx * 4 + j;
            float val = acc[i][j] + bj[j];
            if (mode == 0) {
                out1[(size_t)grow * N + col] = val;
            } else if (mode == 1) {
                if (col < Dc) out1[(size_t)grow * Dc + col] = val;
                else          out2[(size_t)grow * Dc + (col - Dc)] = val;
            } else {
                int q = grow / Bc;
                if (q < RUc) {
                    out1[(size_t)grow * Dc + col] = val;
                } else {
                    val = fminf(10.0f, fmaxf(-10.0f, val));
                    out2[(size_t)(grow - RUc * Bc) * Dc + col] = val;
                }
            }
        }
    }
}

// ---------------- AC scores: w[n,q,k] = dot(qu[n,q,:], rk[n,k,:]) -----------
__global__ void ac_kernel(const float* __restrict__ keyt,
                          const float* __restrict__ pbu) {
    __shared__ float Qs[32][65];
    __shared__ float Ks[32][65];
    int n = blockIdx.z; int b = n >> 3; int h = n & 7;
    int q0 = blockIdx.y * 32, k0 = blockIdx.x * 32;
    int tx = threadIdx.x, ty = threadIdx.y;
    int t = ty * 16 + tx;
    int lr = t >> 3;          // 0..31
    int lc = (t & 7) * 8;     // 0..56

    {
        int q = q0 + lr;
        const float* src = g_query + ((size_t)q * Bc + b) * Dc + h * HDc + lc;
        const float* pu  = pbu + h * HDc + lc;
#pragma unroll
        for (int i = 0; i < 8; i++)
            Qs[lr][lc + i] = (q < Qc) ? (src[i] + pu[i]) : 0.f;
        int k = k0 + lr;
        const float* ks = keyt + ((size_t)k * Bc + b) * Dc + h * HDc + lc;
#pragma unroll
        for (int i = 0; i < 8; i++)
            Ks[lr][lc + i] = ks[i];
    }
    __syncthreads();

    float a00 = 0.f, a01 = 0.f, a10 = 0.f, a11 = 0.f;
#pragma unroll
    for (int d = 0; d < HDc; d++) {
        float q0v = Qs[ty * 2][d],     q1v = Qs[ty * 2 + 1][d];
        float k0v = Ks[tx * 2][d],     k1v = Ks[tx * 2 + 1][d];
        a00 += q0v * k0v; a01 += q0v * k1v;
        a10 += q1v * k0v; a11 += q1v * k1v;
    }
    size_t base = (size_t)n * Qc * KVc;
    int q = q0 + ty * 2, k = k0 + tx * 2;
    if (q < Qc)     { g_w[base + (size_t)q * KVc + k] = a00; g_w[base + (size_t)q * KVc + k + 1] = a01; }
    if (q + 1 < Qc) { g_w[base + (size_t)(q + 1) * KVc + k] = a10; g_w[base + (size_t)(q + 1) * KVc + k + 1] = a11; }
}

// ---------------- BD scores with rel-shift scattered into w -----------------
__global__ void bd_kernel(const float* __restrict__ pbv) {
    __shared__ float Us[32][65];
    __shared__ float Ps[32][65];
    int n = blockIdx.z; int b = n >> 3; int h = n & 7;
    int u0 = blockIdx.y * 32, p0 = blockIdx.x * 32;
    int tx = threadIdx.x, ty = threadIdx.y;
    int t = ty * 16 + tx;
    int lr = t >> 3;
    int lc = (t & 7) * 8;

    {
        int u = u0 + lr;
        const float* src = g_query + ((size_t)(Rc + u) * Bc + b) * Dc + h * HDc + lc;
        const float* pv  = pbv + h * HDc + lc;
#pragma unroll
        for (int i = 0; i < 8; i++)
            Us[lr][lc + i] = src[i] + pv[i];
        int p = p0 + lr;
        const float* ps = g_pos + (size_t)p * Dc + h * HDc + lc;
#pragma unroll
        for (int i = 0; i < 8; i++)
            Ps[lr][lc + i] = (p < PEc) ? ps[i] : 0.f;
    }
    __syncthreads();

    float a00 = 0.f, a01 = 0.f, a10 = 0.f, a11 = 0.f;
#pragma unroll
    for (int d = 0; d < HDc; d++) {
        float u0v = Us[ty * 2][d],   u1v = Us[ty * 2 + 1][d];
        float p0v = Ps[tx * 2][d],   p1v = Ps[tx * 2 + 1][d];
        a00 += u0v * p0v; a01 += u0v * p1v;
        a10 += u1v * p0v; a11 += u1v * p1v;
    }
    size_t base = (size_t)n * Qc * KVc;
    float accs[2][2] = {{a00, a01}, {a10, a11}};
#pragma unroll
    for (int i = 0; i < 2; i++) {
#pragma unroll
        for (int j = 0; j < 2; j++) {
            int u = u0 + ty * 2 + i;
            int p = p0 + tx * 2 + j;
            if (p < PEc) {
                int jj = p - (Uc - 1 - u);
                if (jj >= 0 && jj < Uc)
                    g_w[base + (size_t)(Rc + u) * KVc + (Mc + Rc) + jj] += accs[i][j];
            }
        }
    }
}

// ---------------- scale + masks + softmax (in place, 576 threads/row) -------
__global__ void softmax_kernel(const unsigned* __restrict__ mask,
                               const int* __restrict__ lengths) {
    int q = blockIdx.x;
    int n = blockIdx.y;
    int b = n >> 3;
    int k = threadIdx.x;     // 0..575
    size_t off = (size_t)n * Qc * KVc + (size_t)q * KVc;

    float v = g_w[off + k];
    int cutoff = (Mc + Rc) + lengths[b];   // KV - U + len
    bool m = (mask[q * KVc + k] != 0u) || (k >= cutoff);
    v = m ? NEG_INF_F : v * SCALE_F;

    __shared__ float red[32];
    // max
    float x = v;
#pragma unroll
    for (int o = 16; o > 0; o >>= 1) x = fmaxf(x, __shfl_xor_sync(0xffffffffu, x, o));
    if ((k & 31) == 0) red[k >> 5] = x;
    __syncthreads();
    if (k < 32) {
        float y = (k < 18) ? red[k] : -3.4e38f;
#pragma unroll
        for (int o = 16; o > 0; o >>= 1) y = fmaxf(y, __shfl_xor_sync(0xffffffffu, y, o));
        if (k == 0) red[0] = y;
    }
    __syncthreads();
    float mx = red[0];
    float e = expf(v - mx);
    __syncthreads();
    // sum
    x = e;
#pragma unroll
    for (int o = 16; o > 0; o >>= 1) x += __shfl_xor_sync(0xffffffffu, x, o);
    if ((k & 31) == 0) red[k >> 5] = x;
    __syncthreads();
    if (k < 32) {
        float y = (k < 18) ? red[k] : 0.f;
#pragma unroll
        for (int o = 16; o > 0; o >>= 1) y += __shfl_xor_sync(0xffffffffu, y, o);
        if (k == 0) red[0] = y;
    }
    __syncthreads();
    g_w[off + k] = e / red[0];
}

// ---------------- attn: out[q, b, h*64+d] = sum_k probs * v -----------------
__global__ void attn_kernel(const float* __restrict__ valt) {
    __shared__ float Pr[32][33];
    __shared__ float Vs[32][68];
    int n = blockIdx.z; int b = n >> 3; int h = n & 7;
    int q0 = blockIdx.y * 32;
    int tx = threadIdx.x, ty = threadIdx.y;
    int t = ty * 16 + tx;

    float acc[2][4];
#pragma unroll
    for (int i = 0; i < 2; i++)
#pragma unroll
        for (int j = 0; j < 4; j++) acc[i][j] = 0.f;

    for (int kb = 0; kb < KVc; kb += 32) {
        {
            int lr = t >> 3;
            int lc = (t & 7) * 4;
            int q = q0 + lr;
            const float* ps = &g_w[(size_t)n * Qc * KVc + (size_t)q * KVc + kb + lc];
#pragma unroll
            for (int i = 0; i < 4; i++)
                Pr[lr][lc + i] = (q < Qc) ? ps[i] : 0.f;
            int vr = t >> 3;
            int vc = (t & 7) * 8;
            const float* vs = valt + ((size_t)(kb + vr) * Bc + b) * Dc + h * HDc + vc;
#pragma unroll
            for (int i = 0; i < 8; i++)
                Vs[vr][vc + i] = vs[i];
        }
        __syncthreads();
#pragma unroll
        for (int kk = 0; kk < 32; kk++) {
            float p0 = Pr[ty * 2][kk], p1 = Pr[ty * 2 + 1][kk];
            float4 vv = *(const float4*)&Vs[kk][tx * 4];
            acc[0][0] += p0 * vv.x; acc[0][1] += p0 * vv.y; acc[0][2] += p0 * vv.z; acc[0][3] += p0 * vv.w;
            acc[1][0] += p1 * vv.x; acc[1][1] += p1 * vv.y; acc[1][2] += p1 * vv.z; acc[1][3] += p1 * vv.w;
        }
        __syncthreads();
    }
#pragma unroll
    for (int i = 0; i < 2; i++) {
        int q = q0 + ty * 2 + i;
        if (q >= Qc) continue;
        float* dst = &g_attn[((size_t)q * Bc + b) * Dc + h * HDc + tx * 4];
#pragma unroll
        for (int j = 0; j < 4; j++) dst[j] = acc[i][j];
    }
}

// ---------------- launch ----------------------------------------------------
extern "C" void kernel_launch(void* const* d_in, const int* in_sizes, int n_in,
                              void* d_out, int out_size) {
    const float*    utterance     = (const float*)d_in[0];
    const int*      lengths       = (const int*)d_in[1];
    const float*    right_context = (const float*)d_in[2];
    const float*    summary       = (const float*)d_in[3];
    const float*    memory        = (const float*)d_in[4];
    const unsigned* attn_mask     = (const unsigned*)d_in[5];
    const float*    pos_emb       = (const float*)d_in[6];
    const float*    Wq            = (const float*)d_in[7];
    const float*    bq            = (const float*)d_in[8];
    const float*    Wkv           = (const float*)d_in[9];
    const float*    bkv           = (const float*)d_in[10];
    const float*    Wo            = (const float*)d_in[11];
    const float*    bo            = (const float*)d_in[12];
    const float*    Wpos          = (const float*)d_in[13];
    const float*    pbu           = (const float*)d_in[14];
    const float*    pbv           = (const float*)d_in[15];

    float* out      = (float*)d_out;
    float* out_rcu  = out;                                    // (R+U, B, D)
    float* out_mem  = out + (size_t)RUc * Bc * Dc;            // (S, B, D)
    float* out_key  = out + (size_t)Qc * Bc * Dc;             // (KV, B, D)
    float* out_val  = out_key + (size_t)KVc * Bc * Dc;        // (KV, B, D)

    void *p_qin_, *p_kvin_, *p_query_, *p_pos_, *p_attn_;
    cudaGetSymbolAddress(&p_qin_,  g_qin);
    cudaGetSymbolAddress(&p_kvin_, g_kvin);
    cudaGetSymbolAddress(&p_query_, g_query);
    cudaGetSymbolAddress(&p_pos_,  g_pos);
    cudaGetSymbolAddress(&p_attn_, g_attn);
    float* p_qin   = (float*)p_qin_;
    float* p_kvin  = (float*)p_kvin_;
    float* p_query = (float*)p_query_;
    float* p_pos   = (float*)p_pos_;
    float* p_attn  = (float*)p_attn_;

    dim3 blk16(16, 16);

    // 1) gathers
    gather_qin<<<(Qc * Bc * Dc + 255) / 256, 256>>>(right_context, utterance, summary);
    gather_kvin<<<(KVc * Bc * Dc + 255) / 256, 256>>>(memory, right_context, utterance);

    // 2) projections
    sgemm_nt<<<dim3(Dc / 64, (Qc * Bc) / 64), blk16>>>(p_qin, Wq, bq, Qc * Bc, Dc, Dc, p_query, nullptr, 0);
    sgemm_nt<<<dim3((2 * Dc) / 64, (KVc * Bc) / 64), blk16>>>(p_kvin, Wkv, bkv, KVc * Bc, 2 * Dc, Dc, out_key, out_val, 1);
    sgemm_nt<<<dim3(Dc / 64, (PEc + 63) / 64), blk16>>>(pos_emb, Wpos, nullptr, PEc, Dc, Dc, p_pos, nullptr, 0);

    // 3) scores
    ac_kernel<<<dim3(KVc / 32, (Qc + 31) / 32, BHc), blk16>>>(out_key, pbu);
    bd_kernel<<<dim3((PEc + 31) / 32, Uc / 32, BHc), blk16>>>(pbv);

    // 4) softmax (scale + masks fused)
    softmax_kernel<<<dim3(Qc, BHc), KVc>>>(attn_mask, lengths);

    // 5) probs @ V
    attn_kernel<<<dim3(1, (Qc + 31) / 32, BHc), blk16>>>(out_val);

    // 6) output projection with split + clip
    sgemm_nt<<<dim3(Dc / 64, (Qc * Bc) / 64), blk16>>>(p_attn, Wo, bo, Qc * Bc, Dc, Dc, out_rcu, out_mem, 2);
}

// round 4
// speedup vs baseline: 2.2877x; 2.2877x over previous
#include <cuda_runtime.h>
#include <stdint.h>

#define Uc   512
#define Bc   16
#define Dc   512
#define Hc   8
#define Rc   32
#define Sc   16
#define Mc   32
#define HDc  64
#define Qc   560
#define KVc  576
#define PEc  1023
#define BHc  128
#define RUc  544
#define SCALE_F 0.125f
#define NEG_INF_F -100000000.0f

// ---------------- scratch ---------------------------------------------------
__device__ float g_qin[Qc * Bc * Dc];
__device__ float g_kvin[KVc * Bc * Dc];
__device__ float g_query[Qc * Bc * Dc];
__device__ float g_pos[PEc * Dc];
__device__ float g_w[(size_t)BHc * Qc * KVc];
__device__ float g_attn[Qc * Bc * Dc];

// ---------------- tf32 helpers ---------------------------------------------
__device__ __forceinline__ unsigned f2tf(float x) {
    unsigned r;
    asm("cvt.rna.tf32.f32 %0, %1;" : "=r"(r) : "f"(x));
    return r;
}

__device__ __forceinline__ void mma8(float* c, const unsigned* a, const unsigned* b) {
    asm volatile(
        "mma.sync.aligned.m16n8k8.row.col.f32.tf32.tf32.f32 "
        "{%0,%1,%2,%3},{%4,%5,%6,%7},{%8,%9},{%0,%1,%2,%3};"
        : "+f"(c[0]), "+f"(c[1]), "+f"(c[2]), "+f"(c[3])
        : "r"(a[0]), "r"(a[1]), "r"(a[2]), "r"(a[3]), "r"(b[0]), "r"(b[1]));
}

// ---------------- gathers ---------------------------------------------------
__global__ void gather_qin(const float* __restrict__ rc,
                           const float* __restrict__ utt,
                           const float* __restrict__ summ) {
    int idx = blockIdx.x * blockDim.x + threadIdx.x;
    if (idx >= Qc * Bc * Dc) return;
    int q = idx / (Bc * Dc);
    int rem = idx - q * (Bc * Dc);
    float v;
    if (q < Rc)            v = rc[q * Bc * Dc + rem];
    else if (q < Rc + Uc)  v = utt[(q - Rc) * Bc * Dc + rem];
    else                   v = summ[(q - Rc - Uc) * Bc * Dc + rem];
    g_qin[idx] = v;
}

__global__ void gather_kvin(const float* __restrict__ mem,
                            const float* __restrict__ rc,
                            const float* __restrict__ utt) {
    int idx = blockIdx.x * blockDim.x + threadIdx.x;
    if (idx >= KVc * Bc * Dc) return;
    int q = idx / (Bc * Dc);
    int rem = idx - q * (Bc * Dc);
    float v;
    if (q < Mc)            v = mem[q * Bc * Dc + rem];
    else if (q < Mc + Rc)  v = rc[(q - Mc) * Bc * Dc + rem];
    else                   v = utt[(q - Mc - Rc) * Bc * Dc + rem];
    g_kvin[idx] = v;
}

// ---------------- projection GEMM: C = A(M,K) @ W(N,K)^T + bias -------------
// block tile 128x64, 256 threads, 8 warps (4 m x 2 n), warp tile 32x32
__global__ void __launch_bounds__(256, 2)
proj_mma(const float* __restrict__ A,
         const float* __restrict__ W,
         const float* __restrict__ bias,
         int M, int N, int K,
         float* __restrict__ out1,
         float* __restrict__ out2,
         int mode) {
    __shared__ unsigned As[128][36];
    __shared__ unsigned Bs[64][36];
    const int t = threadIdx.x;
    const int warp = t >> 5, lane = t & 31;
    const int g = lane >> 2, tig = lane & 3;
    const int wm = warp & 3, wn = warp >> 2;
    const int rowBase = blockIdx.y * 128, colBase = blockIdx.x * 64;

    float acc[2][4][4];
#pragma unroll
    for (int mi = 0; mi < 2; mi++)
#pragma unroll
        for (int ni = 0; ni < 4; ni++)
#pragma unroll
            for (int j = 0; j < 4; j++) acc[mi][ni][j] = 0.f;

    for (int k0 = 0; k0 < K; k0 += 32) {
#pragma unroll
        for (int i = 0; i < 4; i++) {
            int idx = t + i * 256;               // 0..1023
            int r = idx >> 3, c4 = (idx & 7) << 2;
            int grow = rowBase + r;
            float4 v = make_float4(0.f, 0.f, 0.f, 0.f);
            if (grow < M) v = *(const float4*)(A + (size_t)grow * K + k0 + c4);
            As[r][c4 + 0] = f2tf(v.x); As[r][c4 + 1] = f2tf(v.y);
            As[r][c4 + 2] = f2tf(v.z); As[r][c4 + 3] = f2tf(v.w);
        }
#pragma unroll
        for (int i = 0; i < 2; i++) {
            int idx = t + i * 256;               // 0..511
            int r = idx >> 3, c4 = (idx & 7) << 2;
            float4 v = *(const float4*)(W + (size_t)(colBase + r) * K + k0 + c4);
            Bs[r][c4 + 0] = f2tf(v.x); Bs[r][c4 + 1] = f2tf(v.y);
            Bs[r][c4 + 2] = f2tf(v.z); Bs[r][c4 + 3] = f2tf(v.w);
        }
        __syncthreads();

#pragma unroll
        for (int ks = 0; ks < 4; ks++) {
            unsigned af[2][4], bf[4][2];
#pragma unroll
            for (int mi = 0; mi < 2; mi++) {
                int r0 = wm * 32 + mi * 16 + g;
                int c0 = ks * 8 + tig;
                af[mi][0] = As[r0][c0];
                af[mi][1] = As[r0 + 8][c0];
                af[mi][2] = As[r0][c0 + 4];
                af[mi][3] = As[r0 + 8][c0 + 4];
            }
#pragma unroll
            for (int ni = 0; ni < 4; ni++) {
                int n0 = wn * 32 + ni * 8 + g;
                int kk = ks * 8 + tig;
                bf[ni][0] = Bs[n0][kk];
                bf[ni][1] = Bs[n0][kk + 4];
            }
#pragma unroll
            for (int mi = 0; mi < 2; mi++)
#pragma unroll
                for (int ni = 0; ni < 4; ni++)
                    mma8(acc[mi][ni], af[mi], bf[ni]);
        }
        __syncthreads();
    }

#pragma unroll
    for (int mi = 0; mi < 2; mi++) {
#pragma unroll
        for (int ni = 0; ni < 4; ni++) {
            int col = colBase + wn * 32 + ni * 8 + 2 * tig;
            float b0 = bias ? bias[col] : 0.f;
            float b1 = bias ? bias[col + 1] : 0.f;
#pragma unroll
            for (int half = 0; half < 2; half++) {
                int row = rowBase + wm * 32 + mi * 16 + g + half * 8;
                if (row >= M) continue;
                float v0 = acc[mi][ni][half * 2 + 0] + b0;
                float v1 = acc[mi][ni][half * 2 + 1] + b1;
                if (mode == 0) {
                    out1[(size_t)row * N + col]     = v0;
                    out1[(size_t)row * N + col + 1] = v1;
                } else if (mode == 1) {
                    if (col < Dc) {
                        out1[(size_t)row * Dc + col]     = v0;
                        out1[(size_t)row * Dc + col + 1] = v1;
                    } else {
                        out2[(size_t)row * Dc + col - Dc]     = v0;
                        out2[(size_t)row * Dc + col - Dc + 1] = v1;
                    }
                } else {
                    int q = row >> 4;
                    if (q < RUc) {
                        out1[(size_t)row * Dc + col]     = v0;
                        out1[(size_t)row * Dc + col + 1] = v1;
                    } else {
                        v0 = fminf(10.0f, fmaxf(-10.0f, v0));
                        v1 = fminf(10.0f, fmaxf(-10.0f, v1));
                        out2[(size_t)(row - RUc * Bc) * Dc + col]     = v0;
                        out2[(size_t)(row - RUc * Bc) * Dc + col + 1] = v1;
                    }
                }
            }
        }
    }
}

// ---------------- AC: w[n,q,k] = (query[q,b,h,:]+pbu[h]) . key[k,b,h,:] -----
__global__ void __launch_bounds__(128, 4)
ac_mma(const float* __restrict__ keyt,
       const float* __restrict__ pbu) {
    __shared__ unsigned As[64][36];
    __shared__ unsigned Bs[64][36];
    const int t = threadIdx.x;
    const int warp = t >> 5, lane = t & 31;
    const int g = lane >> 2, tig = lane & 3;
    const int wm = warp & 1, wn = warp >> 1;
    const int n = blockIdx.z, b = n >> 3, h = n & 7;
    const int rowBase = blockIdx.y * 64, colBase = blockIdx.x * 64;

    float acc[2][4][4];
#pragma unroll
    for (int mi = 0; mi < 2; mi++)
#pragma unroll
        for (int ni = 0; ni < 4; ni++)
#pragma unroll
            for (int j = 0; j < 4; j++) acc[mi][ni][j] = 0.f;

    for (int k0 = 0; k0 < HDc; k0 += 32) {
#pragma unroll
        for (int i = 0; i < 4; i++) {
            int idx = t + i * 128;               // 0..511
            int r = idx >> 3, c4 = (idx & 7) << 2;
            int q = rowBase + r;
            float4 v = make_float4(0.f, 0.f, 0.f, 0.f);
            if (q < Qc) {
                v = *(const float4*)(g_query + ((size_t)q * Bc + b) * Dc + h * HDc + k0 + c4);
                float4 p = *(const float4*)(pbu + h * HDc + k0 + c4);
                v.x += p.x; v.y += p.y; v.z += p.z; v.w += p.w;
            }
            As[r][c4 + 0] = f2tf(v.x); As[r][c4 + 1] = f2tf(v.y);
            As[r][c4 + 2] = f2tf(v.z); As[r][c4 + 3] = f2tf(v.w);
        }
#pragma unroll
        for (int i = 0; i < 4; i++) {
            int idx = t + i * 128;
            int r = idx >> 3, c4 = (idx & 7) << 2;
            int k = colBase + r;
            float4 v = *(const float4*)(keyt + ((size_t)k * Bc + b) * Dc + h * HDc + k0 + c4);
            Bs[r][c4 + 0] = f2tf(v.x); Bs[r][c4 + 1] = f2tf(v.y);
            Bs[r][c4 + 2] = f2tf(v.z); Bs[r][c4 + 3] = f2tf(v.w);
        }
        __syncthreads();

#pragma unroll
        for (int ks = 0; ks < 4; ks++) {
            unsigned af[2][4], bf[4][2];
#pragma unroll
            for (int mi = 0; mi < 2; mi++) {
                int r0 = wm * 32 + mi * 16 + g;
                int c0 = ks * 8 + tig;
                af[mi][0] = As[r0][c0];     af[mi][1] = As[r0 + 8][c0];
                af[mi][2] = As[r0][c0 + 4]; af[mi][3] = As[r0 + 8][c0 + 4];
            }
#pragma unroll
            for (int ni = 0; ni < 4; ni++) {
                int n0 = wn * 32 + ni * 8 + g;
                int kk = ks * 8 + tig;
                bf[ni][0] = Bs[n0][kk];
                bf[ni][1] = Bs[n0][kk + 4];
            }
#pragma unroll
            for (int mi = 0; mi < 2; mi++)
#pragma unroll
                for (int ni = 0; ni < 4; ni++)
                    mma8(acc[mi][ni], af[mi], bf[ni]);
        }
        __syncthreads();
    }

    size_t base = (size_t)n * Qc * KVc;
#pragma unroll
    for (int mi = 0; mi < 2; mi++) {
#pragma unroll
        for (int ni = 0; ni < 4; ni++) {
            int col = colBase + wn * 32 + ni * 8 + 2 * tig;
#pragma unroll
            for (int half = 0; half < 2; half++) {
                int q = rowBase + wm * 32 + mi * 16 + g + half * 8;
                if (q >= Qc) continue;
                g_w[base + (size_t)q * KVc + col]     = acc[mi][ni][half * 2 + 0];
                g_w[base + (size_t)q * KVc + col + 1] = acc[mi][ni][half * 2 + 1];
            }
        }
    }
}

// ---------------- BD with rel-shift scatter-add -----------------------------
__global__ void __launch_bounds__(128, 4)
bd_mma(const float* __restrict__ pbv) {
    __shared__ unsigned As[64][36];
    __shared__ unsigned Bs[64][36];
    const int t = threadIdx.x;
    const int warp = t >> 5, lane = t & 31;
    const int g = lane >> 2, tig = lane & 3;
    const int wm = warp & 1, wn = warp >> 1;
    const int n = blockIdx.z, b = n >> 3, h = n & 7;
    const int rowBase = blockIdx.y * 64;   // u
    const int colBase = blockIdx.x * 64;   // p

    float acc[2][4][4];
#pragma unroll
    for (int mi = 0; mi < 2; mi++)
#pragma unroll
        for (int ni = 0; ni < 4; ni++)
#pragma unroll
            for (int j = 0; j < 4; j++) acc[mi][ni][j] = 0.f;

    for (int k0 = 0; k0 < HDc; k0 += 32) {
#pragma unroll
        for (int i = 0; i < 4; i++) {
            int idx = t + i * 128;
            int r = idx >> 3, c4 = (idx & 7) << 2;
            int u = rowBase + r;
            float4 v = *(const float4*)(g_query + ((size_t)(Rc + u) * Bc + b) * Dc + h * HDc + k0 + c4);
            float4 p = *(const float4*)(pbv + h * HDc + k0 + c4);
            v.x += p.x; v.y += p.y; v.z += p.z; v.w += p.w;
            As[r][c4 + 0] = f2tf(v.x); As[r][c4 + 1] = f2tf(v.y);
            As[r][c4 + 2] = f2tf(v.z); As[r][c4 + 3] = f2tf(v.w);
        }
#pragma unroll
        for (int i = 0; i < 4; i++) {
            int idx = t + i * 128;
            int r = idx >> 3, c4 = (idx & 7) << 2;
            int p = colBase + r;
            float4 v = make_float4(0.f, 0.f, 0.f, 0.f);
            if (p < PEc)
                v = *(const float4*)(g_pos + (size_t)p * Dc + h * HDc + k0 + c4);
            Bs[r][c4 + 0] = f2tf(v.x); Bs[r][c4 + 1] = f2tf(v.y);
            Bs[r][c4 + 2] = f2tf(v.z); Bs[r][c4 + 3] = f2tf(v.w);
        }
        __syncthreads();

#pragma unroll
        for (int ks = 0; ks < 4; ks++) {
            unsigned af[2][4], bf[4][2];
#pragma unroll
            for (int mi = 0; mi < 2; mi++) {
                int r0 = wm * 32 + mi * 16 + g;
                int c0 = ks * 8 + tig;
                af[mi][0] = As[r0][c0];     af[mi][1] = As[r0 + 8][c0];
                af[mi][2] = As[r0][c0 + 4]; af[mi][3] = As[r0 + 8][c0 + 4];
            }
#pragma unroll
            for (int ni = 0; ni < 4; ni++) {
                int n0 = wn * 32 + ni * 8 + g;
                int kk = ks * 8 + tig;
                bf[ni][0] = Bs[n0][kk];
                bf[ni][1] = Bs[n0][kk + 4];
            }
#pragma unroll
            for (int mi = 0; mi < 2; mi++)
#pragma unroll
                for (int ni = 0; ni < 4; ni++)
                    mma8(acc[mi][ni], af[mi], bf[ni]);
        }
        __syncthreads();
    }

    size_t base = (size_t)n * Qc * KVc;
#pragma unroll
    for (int mi = 0; mi < 2; mi++) {
#pragma unroll
        for (int ni = 0; ni < 4; ni++) {
#pragma unroll
            for (int half = 0; half < 2; half++) {
                int u = rowBase + wm * 32 + mi * 16 + g + half * 8;
#pragma unroll
                for (int jc = 0; jc < 2; jc++) {
                    int p = colBase + wn * 32 + ni * 8 + 2 * tig + jc;
                    if (p >= PEc) continue;
                    int jj = p + u - (Uc - 1);
                    if (jj >= 0 && jj < Uc)
                        g_w[base + (size_t)(Rc + u) * KVc + (Mc + Rc) + jj] +=
                            acc[mi][ni][half * 2 + jc];
                }
            }
        }
    }
}

// ---------------- softmax (scale + masks fused, in place) -------------------
__global__ void softmax_kernel(const unsigned* __restrict__ mask,
                               const int* __restrict__ lengths) {
    int q = blockIdx.x;
    int n = blockIdx.y;
    int b = n >> 3;
    int k = threadIdx.x;
    size_t off = (size_t)n * Qc * KVc + (size_t)q * KVc;

    float v = g_w[off + k];
    int cutoff = (Mc + Rc) + lengths[b];
    bool m = (mask[q * KVc + k] != 0u) || (k >= cutoff);
    v = m ? NEG_INF_F : v * SCALE_F;

    __shared__ float red[32];
    float x = v;
#pragma unroll
    for (int o = 16; o > 0; o >>= 1) x = fmaxf(x, __shfl_xor_sync(0xffffffffu, x, o));
    if ((k & 31) == 0) red[k >> 5] = x;
    __syncthreads();
    if (k < 32) {
        float y = (k < 18) ? red[k] : -3.4e38f;
#pragma unroll
        for (int o = 16; o > 0; o >>= 1) y = fmaxf(y, __shfl_xor_sync(0xffffffffu, y, o));
        if (k == 0) red[0] = y;
    }
    __syncthreads();
    float mx = red[0];
    float e = __expf(v - mx);
    __syncthreads();
    x = e;
#pragma unroll
    for (int o = 16; o > 0; o >>= 1) x += __shfl_xor_sync(0xffffffffu, x, o);
    if ((k & 31) == 0) red[k >> 5] = x;
    __syncthreads();
    if (k < 32) {
        float y = (k < 18) ? red[k] : 0.f;
#pragma unroll
        for (int o = 16; o > 0; o >>= 1) y += __shfl_xor_sync(0xffffffffu, y, o);
        if (k == 0) red[0] = y;
    }
    __syncthreads();
    g_w[off + k] = e / red[0];
}

// ---------------- PV: attn[q,b,h*64+d] = sum_k probs[n,q,k] * v[k,b,h,d] ----
__global__ void __launch_bounds__(128, 4)
pv_mma(const float* __restrict__ valt) {
    __shared__ unsigned As[64][36];
    __shared__ unsigned Bs[32][72];
    const int t = threadIdx.x;
    const int warp = t >> 5, lane = t & 31;
    const int g = lane >> 2, tig = lane & 3;
    const int wm = warp & 1, wn = warp >> 1;
    const int n = blockIdx.z, b = n >> 3, h = n & 7;
    const int rowBase = blockIdx.y * 64;

    float acc[2][4][4];
#pragma unroll
    for (int mi = 0; mi < 2; mi++)
#pragma unroll
        for (int ni = 0; ni < 4; ni++)
#pragma unroll
            for (int j = 0; j < 4; j++) acc[mi][ni][j] = 0.f;

    for (int k0 = 0; k0 < KVc; k0 += 32) {
#pragma unroll
        for (int i = 0; i < 4; i++) {
            int idx = t + i * 128;               // A: 64 rows x 32 k
            int r = idx >> 3, c4 = (idx & 7) << 2;
            int q = rowBase + r;
            float4 v = make_float4(0.f, 0.f, 0.f, 0.f);
            if (q < Qc)
                v = *(const float4*)(g_w + (size_t)n * Qc * KVc + (size_t)q * KVc + k0 + c4);
            As[r][c4 + 0] = f2tf(v.x); As[r][c4 + 1] = f2tf(v.y);
            As[r][c4 + 2] = f2tf(v.z); As[r][c4 + 3] = f2tf(v.w);
        }
#pragma unroll
        for (int i = 0; i < 4; i++) {
            int idx = t + i * 128;               // B: 32 k-rows x 64 d
            int r = idx >> 4, c4 = (idx & 15) << 2;
            float4 v = *(const float4*)(valt + ((size_t)(k0 + r) * Bc + b) * Dc + h * HDc + c4);
            Bs[r][c4 + 0] = f2tf(v.x); Bs[r][c4 + 1] = f2tf(v.y);
            Bs[r][c4 + 2] = f2tf(v.z); Bs[r][c4 + 3] = f2tf(v.w);
        }
        __syncthreads();

#pragma unroll
        for (int ks = 0; ks < 4; ks++) {
            unsigned af[2][4], bf[4][2];
#pragma unroll
            for (int mi = 0; mi < 2; mi++) {
                int r0 = wm * 32 + mi * 16 + g;
                int c0 = ks * 8 + tig;
                af[mi][0] = As[r0][c0];     af[mi][1] = As[r0 + 8][c0];
                af[mi][2] = As[r0][c0 + 4]; af[mi][3] = As[r0 + 8][c0 + 4];
            }
#pragma unroll
            for (int ni = 0; ni < 4; ni++) {
                int col = wn * 32 + ni * 8 + g;
                int kk = ks * 8 + tig;
                bf[ni][0] = Bs[kk][col];
                bf[ni][1] = Bs[kk + 4][col];
            }
#pragma unroll
            for (int mi = 0; mi < 2; mi++)
#pragma unroll
                for (int ni = 0; ni < 4; ni++)
                    mma8(acc[mi][ni], af[mi], bf[ni]);
        }
        __syncthreads();
    }

#pragma unroll
    for (int mi = 0; mi < 2; mi++) {
#pragma unroll
        for (int ni = 0; ni < 4; ni++) {
            int col = wn * 32 + ni * 8 + 2 * tig;
#pragma unroll
            for (int half = 0; half < 2; half++) {
                int q = rowBase + wm * 32 + mi * 16 + g + half * 8;
                if (q >= Qc) continue;
                float* dst = g_attn + ((size_t)q * Bc + b) * Dc + h * HDc + col;
                dst[0] = acc[mi][ni][half * 2 + 0];
                dst[1] = acc[mi][ni][half * 2 + 1];
            }
        }
    }
}

// ---------------- launch ----------------------------------------------------
extern "C" void kernel_launch(void* const* d_in, const int* in_sizes, int n_in,
                              void* d_out, int out_size) {
    const float*    utterance     = (const float*)d_in[0];
    const int*      lengths       = (const int*)d_in[1];
    const float*    right_context = (const float*)d_in[2];
    const float*    summary       = (const float*)d_in[3];
    const float*    memory        = (const float*)d_in[4];
    const unsigned* attn_mask     = (const unsigned*)d_in[5];
    const float*    pos_emb       = (const float*)d_in[6];
    const float*    Wq            = (const float*)d_in[7];
    const float*    bq            = (const float*)d_in[8];
    const float*    Wkv           = (const float*)d_in[9];
    const float*    bkv           = (const float*)d_in[10];
    const float*    Wo            = (const float*)d_in[11];
    const float*    bo            = (const float*)d_in[12];
    const float*    Wpos          = (const float*)d_in[13];
    const float*    pbu           = (const float*)d_in[14];
    const float*    pbv           = (const float*)d_in[15];

    float* out      = (float*)d_out;
    float* out_rcu  = out;                                    // (R+U, B, D)
    float* out_mem  = out + (size_t)RUc * Bc * Dc;            // (S, B, D)
    float* out_key  = out + (size_t)Qc * Bc * Dc;             // (KV, B, D)
    float* out_val  = out_key + (size_t)KVc * Bc * Dc;        // (KV, B, D)

    void *p_qin_, *p_query_, *p_pos_, *p_attn_, *p_kvin_;
    cudaGetSymbolAddress(&p_qin_,  g_qin);
    cudaGetSymbolAddress(&p_kvin_, g_kvin);
    cudaGetSymbolAddress(&p_query_, g_query);
    cudaGetSymbolAddress(&p_pos_,  g_pos);
    cudaGetSymbolAddress(&p_attn_, g_attn);
    float* p_qin   = (float*)p_qin_;
    float* p_kvin  = (float*)p_kvin_;
    float* p_query = (float*)p_query_;
    float* p_pos   = (float*)p_pos_;
    float* p_attn  = (float*)p_attn_;

    // 1) gathers
    gather_qin<<<(Qc * Bc * Dc + 255) / 256, 256>>>(right_context, utterance, summary);
    gather_kvin<<<(KVc * Bc * Dc + 255) / 256, 256>>>(memory, right_context, utterance);

    // 2) projections (tf32 MMA)
    proj_mma<<<dim3(Dc / 64, (Qc * Bc) / 128), 256>>>(p_qin, Wq, bq, Qc * Bc, Dc, Dc, p_query, nullptr, 0);
    proj_mma<<<dim3((2 * Dc) / 64, (KVc * Bc) / 128), 256>>>(p_kvin, Wkv, bkv, KVc * Bc, 2 * Dc, Dc, out_key, out_val, 1);
    proj_mma<<<dim3(Dc / 64, (PEc + 127) / 128), 256>>>(pos_emb, Wpos, nullptr, PEc, Dc, Dc, p_pos, nullptr, 0);

    // 3) scores
    ac_mma<<<dim3(KVc / 64, (Qc + 63) / 64, BHc), 128>>>(out_key, pbu);
    bd_mma<<<dim3((PEc + 63) / 64, Uc / 64, BHc), 128>>>(pbv);

    // 4) softmax
    softmax_kernel<<<dim3(Qc, BHc), KVc>>>(attn_mask, lengths);

    // 5) probs @ V
    pv_mma<<<dim3(1, (Qc + 63) / 64, BHc), 128>>>(out_val);

    // 6) output projection with split + clip
    proj_mma<<<dim3(Dc / 64, (Qc * Bc) / 128), 256>>>(p_attn, Wo, bo, Qc * Bc, Dc, Dc, out_rcu, out_mem, 2);
}

// round 5
// speedup vs baseline: 2.9648x; 1.2960x over previous
#include <cuda_runtime.h>
#include <stdint.h>

#define Uc   512
#define Bc   16
#define Dc   512
#define Hc   8
#define Rc   32
#define Sc   16
#define Mc   32
#define HDc  64
#define Qc   560
#define KVc  576
#define PEc  1023
#define BHc  128
#define RUc  544
#define SCALE_F 0.125f
#define NEG_INF_F -100000000.0f

// ---------------- scratch ---------------------------------------------------
__device__ float g_qin[Qc * Bc * Dc];
__device__ float g_kvin[KVc * Bc * Dc];
__device__ float g_query[Qc * Bc * Dc];
__device__ float g_pos[PEc * Dc];
__device__ float g_bd[(size_t)BHc * Uc * Uc];   // dense rel-shifted bd scores
__device__ float g_attn[Qc * Bc * Dc];

// ---------------- tf32 helpers ---------------------------------------------
__device__ __forceinline__ unsigned f2tf(float x) {
    unsigned r;
    asm("cvt.rna.tf32.f32 %0, %1;" : "=r"(r) : "f"(x));
    return r;
}

__device__ __forceinline__ void mma8(float* c, const unsigned* a, const unsigned* b) {
    asm volatile(
        "mma.sync.aligned.m16n8k8.row.col.f32.tf32.tf32.f32 "
        "{%0,%1,%2,%3},{%4,%5,%6,%7},{%8,%9},{%0,%1,%2,%3};"
        : "+f"(c[0]), "+f"(c[1]), "+f"(c[2]), "+f"(c[3])
        : "r"(a[0]), "r"(a[1]), "r"(a[2]), "r"(a[3]), "r"(b[0]), "r"(b[1]));
}

// ---------------- gathers ---------------------------------------------------
__global__ void gather_qin(const float* __restrict__ rc,
                           const float* __restrict__ utt,
                           const float* __restrict__ summ) {
    int idx = blockIdx.x * blockDim.x + threadIdx.x;
    if (idx >= Qc * Bc * Dc) return;
    int q = idx / (Bc * Dc);
    int rem = idx - q * (Bc * Dc);
    float v;
    if (q < Rc)            v = rc[q * Bc * Dc + rem];
    else if (q < Rc + Uc)  v = utt[(q - Rc) * Bc * Dc + rem];
    else                   v = summ[(q - Rc - Uc) * Bc * Dc + rem];
    g_qin[idx] = v;
}

__global__ void gather_kvin(const float* __restrict__ mem,
                            const float* __restrict__ rc,
                            const float* __restrict__ utt) {
    int idx = blockIdx.x * blockDim.x + threadIdx.x;
    if (idx >= KVc * Bc * Dc) return;
    int q = idx / (Bc * Dc);
    int rem = idx - q * (Bc * Dc);
    float v;
    if (q < Mc)            v = mem[q * Bc * Dc + rem];
    else if (q < Mc + Rc)  v = rc[(q - Mc) * Bc * Dc + rem];
    else                   v = utt[(q - Mc - Rc) * Bc * Dc + rem];
    g_kvin[idx] = v;
}

// ---------------- projection GEMM: C = A(M,K) @ W(N,K)^T + bias -------------
__global__ void __launch_bounds__(256, 2)
proj_mma(const float* __restrict__ A,
         const float* __restrict__ W,
         const float* __restrict__ bias,
         int M, int N, int K,
         float* __restrict__ out1,
         float* __restrict__ out2,
         int mode) {
    __shared__ unsigned As[128][36];
    __shared__ unsigned Bs[64][36];
    const int t = threadIdx.x;
    const int warp = t >> 5, lane = t & 31;
    const int g = lane >> 2, tig = lane & 3;
    const int wm = warp & 3, wn = warp >> 2;
    const int rowBase = blockIdx.y * 128, colBase = blockIdx.x * 64;

    float acc[2][4][4];
#pragma unroll
    for (int mi = 0; mi < 2; mi++)
#pragma unroll
        for (int ni = 0; ni < 4; ni++)
#pragma unroll
            for (int j = 0; j < 4; j++) acc[mi][ni][j] = 0.f;

    for (int k0 = 0; k0 < K; k0 += 32) {
#pragma unroll
        for (int i = 0; i < 4; i++) {
            int idx = t + i * 256;
            int r = idx >> 3, c4 = (idx & 7) << 2;
            int grow = rowBase + r;
            float4 v = make_float4(0.f, 0.f, 0.f, 0.f);
            if (grow < M) v = *(const float4*)(A + (size_t)grow * K + k0 + c4);
            As[r][c4 + 0] = f2tf(v.x); As[r][c4 + 1] = f2tf(v.y);
            As[r][c4 + 2] = f2tf(v.z); As[r][c4 + 3] = f2tf(v.w);
        }
#pragma unroll
        for (int i = 0; i < 2; i++) {
            int idx = t + i * 256;
            int r = idx >> 3, c4 = (idx & 7) << 2;
            float4 v = *(const float4*)(W + (size_t)(colBase + r) * K + k0 + c4);
            Bs[r][c4 + 0] = f2tf(v.x); Bs[r][c4 + 1] = f2tf(v.y);
            Bs[r][c4 + 2] = f2tf(v.z); Bs[r][c4 + 3] = f2tf(v.w);
        }
        __syncthreads();

#pragma unroll
        for (int ks = 0; ks < 4; ks++) {
            unsigned af[2][4], bf[4][2];
#pragma unroll
            for (int mi = 0; mi < 2; mi++) {
                int r0 = wm * 32 + mi * 16 + g;
                int c0 = ks * 8 + tig;
                af[mi][0] = As[r0][c0];
                af[mi][1] = As[r0 + 8][c0];
                af[mi][2] = As[r0][c0 + 4];
                af[mi][3] = As[r0 + 8][c0 + 4];
            }
#pragma unroll
            for (int ni = 0; ni < 4; ni++) {
                int n0 = wn * 32 + ni * 8 + g;
                int kk = ks * 8 + tig;
                bf[ni][0] = Bs[n0][kk];
                bf[ni][1] = Bs[n0][kk + 4];
            }
#pragma unroll
            for (int mi = 0; mi < 2; mi++)
#pragma unroll
                for (int ni = 0; ni < 4; ni++)
                    mma8(acc[mi][ni], af[mi], bf[ni]);
        }
        __syncthreads();
    }

#pragma unroll
    for (int mi = 0; mi < 2; mi++) {
#pragma unroll
        for (int ni = 0; ni < 4; ni++) {
            int col = colBase + wn * 32 + ni * 8 + 2 * tig;
            float b0 = bias ? bias[col] : 0.f;
            float b1 = bias ? bias[col + 1] : 0.f;
#pragma unroll
            for (int half = 0; half < 2; half++) {
                int row = rowBase + wm * 32 + mi * 16 + g + half * 8;
                if (row >= M) continue;
                float v0 = acc[mi][ni][half * 2 + 0] + b0;
                float v1 = acc[mi][ni][half * 2 + 1] + b1;
                if (mode == 0) {
                    out1[(size_t)row * N + col]     = v0;
                    out1[(size_t)row * N + col + 1] = v1;
                } else if (mode == 1) {
                    if (col < Dc) {
                        out1[(size_t)row * Dc + col]     = v0;
                        out1[(size_t)row * Dc + col + 1] = v1;
                    } else {
                        out2[(size_t)row * Dc + col - Dc]     = v0;
                        out2[(size_t)row * Dc + col - Dc + 1] = v1;
                    }
                } else {
                    int q = row >> 4;
                    if (q < RUc) {
                        out1[(size_t)row * Dc + col]     = v0;
                        out1[(size_t)row * Dc + col + 1] = v1;
                    } else {
                        v0 = fminf(10.0f, fmaxf(-10.0f, v0));
                        v1 = fminf(10.0f, fmaxf(-10.0f, v1));
                        out2[(size_t)(row - RUc * Bc) * Dc + col]     = v0;
                        out2[(size_t)(row - RUc * Bc) * Dc + col + 1] = v1;
                    }
                }
            }
        }
    }
}

// ---------------- BD dense: g_bd[n][u][jj] = dot(qv_u, pos_{jj+511-u}) ------
// GEMM over (u, p) tiles, stored shifted (jj = p + u - 511). Only the 9
// p-tiles per u-tile that can produce valid jj are launched.
__global__ void __launch_bounds__(128, 4)
bd_dense(const float* __restrict__ pbv) {
    __shared__ unsigned As[64][36];
    __shared__ unsigned Bs[64][36];
    const int t = threadIdx.x;
    const int warp = t >> 5, lane = t & 31;
    const int g = lane >> 2, tig = lane & 3;
    const int wm = warp & 1, wn = warp >> 1;
    const int n = blockIdx.z, b = n >> 3, h = n & 7;
    const int rowBase = blockIdx.y * 64;                      // u0
    const int colBase = 448 - rowBase + blockIdx.x * 64;      // p0 (>= 0)

    float acc[2][4][4];
#pragma unroll
    for (int mi = 0; mi < 2; mi++)
#pragma unroll
        for (int ni = 0; ni < 4; ni++)
#pragma unroll
            for (int j = 0; j < 4; j++) acc[mi][ni][j] = 0.f;

    for (int k0 = 0; k0 < HDc; k0 += 32) {
#pragma unroll
        for (int i = 0; i < 4; i++) {
            int idx = t + i * 128;
            int r = idx >> 3, c4 = (idx & 7) << 2;
            int u = rowBase + r;
            float4 v = *(const float4*)(g_query + ((size_t)(Rc + u) * Bc + b) * Dc + h * HDc + k0 + c4);
            float4 p = *(const float4*)(pbv + h * HDc + k0 + c4);
            v.x += p.x; v.y += p.y; v.z += p.z; v.w += p.w;
            As[r][c4 + 0] = f2tf(v.x); As[r][c4 + 1] = f2tf(v.y);
            As[r][c4 + 2] = f2tf(v.z); As[r][c4 + 3] = f2tf(v.w);
        }
#pragma unroll
        for (int i = 0; i < 4; i++) {
            int idx = t + i * 128;
            int r = idx >> 3, c4 = (idx & 7) << 2;
            int p = colBase + r;
            float4 v = make_float4(0.f, 0.f, 0.f, 0.f);
            if (p < PEc)
                v = *(const float4*)(g_pos + (size_t)p * Dc + h * HDc + k0 + c4);
            Bs[r][c4 + 0] = f2tf(v.x); Bs[r][c4 + 1] = f2tf(v.y);
            Bs[r][c4 + 2] = f2tf(v.z); Bs[r][c4 + 3] = f2tf(v.w);
        }
        __syncthreads();

#pragma unroll
        for (int ks = 0; ks < 4; ks++) {
            unsigned af[2][4], bf[4][2];
#pragma unroll
            for (int mi = 0; mi < 2; mi++) {
                int r0 = wm * 32 + mi * 16 + g;
                int c0 = ks * 8 + tig;
                af[mi][0] = As[r0][c0];     af[mi][1] = As[r0 + 8][c0];
                af[mi][2] = As[r0][c0 + 4]; af[mi][3] = As[r0 + 8][c0 + 4];
            }
#pragma unroll
            for (int ni = 0; ni < 4; ni++) {
                int n0 = wn * 32 + ni * 8 + g;
                int kk = ks * 8 + tig;
                bf[ni][0] = Bs[n0][kk];
                bf[ni][1] = Bs[n0][kk + 4];
            }
#pragma unroll
            for (int mi = 0; mi < 2; mi++)
#pragma unroll
                for (int ni = 0; ni < 4; ni++)
                    mma8(acc[mi][ni], af[mi], bf[ni]);
        }
        __syncthreads();
    }

#pragma unroll
    for (int mi = 0; mi < 2; mi++) {
#pragma unroll
        for (int half = 0; half < 2; half++) {
            int u = rowBase + wm * 32 + mi * 16 + g + half * 8;
#pragma unroll
            for (int ni = 0; ni < 4; ni++) {
#pragma unroll
                for (int jc = 0; jc < 2; jc++) {
                    int p = colBase + wn * 32 + ni * 8 + 2 * tig + jc;
                    if (p >= PEc) continue;
                    int jj = p + u - (Uc - 1);
                    if (jj >= 0 && jj < Uc)
                        g_bd[((size_t)n * Uc + u) * Uc + jj] = acc[mi][ni][half * 2 + jc];
                }
            }
        }
    }
}

// ---------------- fused attention: S = QK^T + bd, softmax, O = P V ----------
// One block per (n, 64-row q-tile). 128 threads, 4 warps (2 q x 2 k/d).
__global__ void __launch_bounds__(128)
fused_attn(const float* __restrict__ keyt,
           const float* __restrict__ valt,
           const float* __restrict__ pbu,
           const unsigned* __restrict__ mask,
           const int* __restrict__ lengths) {
    extern __shared__ unsigned char dynsmem[];
    unsigned (*Qs)[68] = (unsigned (*)[68])(dynsmem);             // 64x68 = 17408B
    unsigned (*Ks)[68] = (unsigned (*)[68])(dynsmem + 17408);     // 17408B
    unsigned (*Vs)[72] = (unsigned (*)[72])(dynsmem + 34816);     // 18432B
    unsigned (*Ps)[68] = (unsigned (*)[68])(dynsmem + 53248);     // 17408B
    __shared__ float redm[2][64];
    __shared__ float reds[2][64];

    const int t = threadIdx.x;
    const int warp = t >> 5, lane = t & 31;
    const int g = lane >> 2, tig = lane & 3;
    const int wm = warp & 1, wn = warp >> 1;
    const int qBase = blockIdx.x * 64;
    const int n = blockIdx.y, b = n >> 3, h = n & 7;
    const int cutoff = (Mc + Rc) + lengths[b];

    // load Q tile (+pbu) once
#pragma unroll
    for (int i = 0; i < 8; i++) {
        int idx = t + i * 128;
        int r = idx >> 4, c4 = (idx & 15) << 2;
        int q = qBase + r;
        float4 v = make_float4(0.f, 0.f, 0.f, 0.f);
        if (q < Qc) {
            v = *(const float4*)(g_query + ((size_t)q * Bc + b) * Dc + h * HDc + c4);
            float4 p = *(const float4*)(pbu + h * HDc + c4);
            v.x += p.x; v.y += p.y; v.z += p.z; v.w += p.w;
        }
        Qs[r][c4 + 0] = f2tf(v.x); Qs[r][c4 + 1] = f2tf(v.y);
        Qs[r][c4 + 2] = f2tf(v.z); Qs[r][c4 + 3] = f2tf(v.w);
    }

    float o[2][4][4];
#pragma unroll
    for (int mi = 0; mi < 2; mi++)
#pragma unroll
        for (int ni = 0; ni < 4; ni++)
#pragma unroll
            for (int j = 0; j < 4; j++) o[mi][ni][j] = 0.f;
    float mrun[2][2], lrun[2][2];
#pragma unroll
    for (int mi = 0; mi < 2; mi++)
#pragma unroll
        for (int hf = 0; hf < 2; hf++) { mrun[mi][hf] = -3.0e38f; lrun[mi][hf] = 0.f; }

    for (int kt = 0; kt < KVc / 64; kt++) {
        const int k0 = kt * 64;
        __syncthreads();   // previous iteration's MMA reads done

        // load K, V tiles (64 k-rows x 64 d)
#pragma unroll
        for (int i = 0; i < 8; i++) {
            int idx = t + i * 128;
            int r = idx >> 4, c4 = (idx & 15) << 2;
            size_t goff = ((size_t)(k0 + r) * Bc + b) * Dc + h * HDc + c4;
            float4 kv = *(const float4*)(keyt + goff);
            Ks[r][c4 + 0] = f2tf(kv.x); Ks[r][c4 + 1] = f2tf(kv.y);
            Ks[r][c4 + 2] = f2tf(kv.z); Ks[r][c4 + 3] = f2tf(kv.w);
            float4 vv = *(const float4*)(valt + goff);
            Vs[r][c4 + 0] = f2tf(vv.x); Vs[r][c4 + 1] = f2tf(vv.y);
            Vs[r][c4 + 2] = f2tf(vv.z); Vs[r][c4 + 3] = f2tf(vv.w);
        }
        __syncthreads();

        // S = Q K^T (64q x 64k, K over d=64)
        float s[2][4][4];
#pragma unroll
        for (int mi = 0; mi < 2; mi++)
#pragma unroll
            for (int ni = 0; ni < 4; ni++)
#pragma unroll
                for (int j = 0; j < 4; j++) s[mi][ni][j] = 0.f;
#pragma unroll
        for (int ks = 0; ks < 8; ks++) {
            unsigned af[2][4], bf[4][2];
#pragma unroll
            for (int mi = 0; mi < 2; mi++) {
                int r0 = wm * 32 + mi * 16 + g;
                int c0 = ks * 8 + tig;
                af[mi][0] = Qs[r0][c0];     af[mi][1] = Qs[r0 + 8][c0];
                af[mi][2] = Qs[r0][c0 + 4]; af[mi][3] = Qs[r0 + 8][c0 + 4];
            }
#pragma unroll
            for (int ni = 0; ni < 4; ni++) {
                int n0 = wn * 32 + ni * 8 + g;
                int kk = ks * 8 + tig;
                bf[ni][0] = Ks[n0][kk];
                bf[ni][1] = Ks[n0][kk + 4];
            }
#pragma unroll
            for (int mi = 0; mi < 2; mi++)
#pragma unroll
                for (int ni = 0; ni < 4; ni++)
                    mma8(s[mi][ni], af[mi], bf[ni]);
        }

        // epilogue: + bd, scale, mask, cutoff
        const bool hasbd = (kt >= 1);   // k >= 64 for all cols
#pragma unroll
        for (int mi = 0; mi < 2; mi++)
#pragma unroll
            for (int j = 0; j < 4; j++) {
                int row = wm * 32 + mi * 16 + (j >> 1) * 8 + g;
                int q = qBase + row;
                bool qbd = hasbd && (q >= Rc) && (q < Rc + Uc);
#pragma unroll
                for (int ni = 0; ni < 4; ni++) {
                    int col = wn * 32 + ni * 8 + 2 * tig + (j & 1);
                    int k = k0 + col;
                    float v = s[mi][ni][j];
                    if (qbd)
                        v += g_bd[((size_t)n * Uc + (q - Rc)) * Uc + (k - (Mc + Rc))];
                    v *= SCALE_F;
                    bool msk = true;
                    if (q < Qc)
                        msk = (mask[q * KVc + k] != 0u) || (k >= cutoff);
                    s[mi][ni][j] = msk ? NEG_INF_F : v;
                }
            }

        // row max (per thread -> tig shuffle -> cross-warp via smem)
        float pm[2][2];
#pragma unroll
        for (int mi = 0; mi < 2; mi++)
#pragma unroll
            for (int hf = 0; hf < 2; hf++) {
                float x = -3.4e38f;
#pragma unroll
                for (int ni = 0; ni < 4; ni++)
                    x = fmaxf(x, fmaxf(s[mi][ni][2 * hf], s[mi][ni][2 * hf + 1]));
                x = fmaxf(x, __shfl_xor_sync(0xffffffffu, x, 1));
                x = fmaxf(x, __shfl_xor_sync(0xffffffffu, x, 2));
                pm[mi][hf] = x;
                if (tig == 0) redm[wn][wm * 32 + mi * 16 + hf * 8 + g] = x;
            }
        __syncthreads();

        float mnew[2][2], fac[2][2];
#pragma unroll
        for (int mi = 0; mi < 2; mi++)
#pragma unroll
            for (int hf = 0; hf < 2; hf++) {
                int row = wm * 32 + mi * 16 + hf * 8 + g;
                float mt = fmaxf(redm[0][row], redm[1][row]);
                float mn = fmaxf(mrun[mi][hf], mt);
                fac[mi][hf] = __expf(mrun[mi][hf] - mn);
                mnew[mi][hf] = mn;
            }

        // exp + per-warp row sums
#pragma unroll
        for (int mi = 0; mi < 2; mi++)
#pragma unroll
            for (int hf = 0; hf < 2; hf++) {
                float ssum = 0.f;
#pragma unroll
                for (int ni = 0; ni < 4; ni++) {
#pragma unroll
                    for (int c = 0; c < 2; c++) {
                        float p = __expf(s[mi][ni][2 * hf + c] - mnew[mi][hf]);
                        s[mi][ni][2 * hf + c] = p;
                        ssum += p;
                    }
                }
                ssum += __shfl_xor_sync(0xffffffffu, ssum, 1);
                ssum += __shfl_xor_sync(0xffffffffu, ssum, 2);
                if (tig == 0) reds[wn][wm * 32 + mi * 16 + hf * 8 + g] = ssum;
            }

        // rescale O accumulators
#pragma unroll
        for (int mi = 0; mi < 2; mi++)
#pragma unroll
            for (int ni = 0; ni < 4; ni++)
#pragma unroll
                for (int j = 0; j < 4; j++)
                    o[mi][ni][j] *= fac[mi][j >> 1];

        // write P tile to smem (tf32)
#pragma unroll
        for (int mi = 0; mi < 2; mi++)
#pragma unroll
            for (int j = 0; j < 4; j++) {
                int row = wm * 32 + mi * 16 + (j >> 1) * 8 + g;
#pragma unroll
                for (int ni = 0; ni < 4; ni++) {
                    int col = wn * 32 + ni * 8 + 2 * tig + (j & 1);
                    Ps[row][col] = f2tf(s[mi][ni][j]);
                }
            }
        __syncthreads();

        // update l, m
#pragma unroll
        for (int mi = 0; mi < 2; mi++)
#pragma unroll
            for (int hf = 0; hf < 2; hf++) {
                int row = wm * 32 + mi * 16 + hf * 8 + g;
                lrun[mi][hf] = lrun[mi][hf] * fac[mi][hf] + reds[0][row] + reds[1][row];
                mrun[mi][hf] = mnew[mi][hf];
            }

        // O += P V  (64q x 64d, K over k=64)
#pragma unroll
        for (int ks = 0; ks < 8; ks++) {
            unsigned af[2][4], bf[4][2];
#pragma unroll
            for (int mi = 0; mi < 2; mi++) {
                int r0 = wm * 32 + mi * 16 + g;
                int c0 = ks * 8 + tig;
                af[mi][0] = Ps[r0][c0];     af[mi][1] = Ps[r0 + 8][c0];
                af[mi][2] = Ps[r0][c0 + 4]; af[mi][3] = Ps[r0 + 8][c0 + 4];
            }
#pragma unroll
            for (int ni = 0; ni < 4; ni++) {
                int col = wn * 32 + ni * 8 + g;
                int kk = ks * 8 + tig;
                bf[ni][0] = Vs[kk][col];
                bf[ni][1] = Vs[kk + 4][col];
            }
#pragma unroll
            for (int mi = 0; mi < 2; mi++)
#pragma unroll
                for (int ni = 0; ni < 4; ni++)
                    mma8(o[mi][ni], af[mi], bf[ni]);
        }
    }

    // final: O / l -> g_attn
#pragma unroll
    for (int mi = 0; mi < 2; mi++)
#pragma unroll
        for (int j = 0; j < 4; j++) {
            int row = wm * 32 + mi * 16 + (j >> 1) * 8 + g;
            int q = qBase + row;
            if (q >= Qc) continue;
            float inv = 1.0f / lrun[mi][j >> 1];
#pragma unroll
            for (int ni = 0; ni < 4; ni++) {
                int d = wn * 32 + ni * 8 + 2 * tig + (j & 1);
                g_attn[((size_t)q * Bc + b) * Dc + h * HDc + d] = o[mi][ni][j] * inv;
            }
        }
}

// ---------------- launch ----------------------------------------------------
extern "C" void kernel_launch(void* const* d_in, const int* in_sizes, int n_in,
                              void* d_out, int out_size) {
    const float*    utterance     = (const float*)d_in[0];
    const int*      lengths       = (const int*)d_in[1];
    const float*    right_context = (const float*)d_in[2];
    const float*    summary       = (const float*)d_in[3];
    const float*    memory        = (const float*)d_in[4];
    const unsigned* attn_mask     = (const unsigned*)d_in[5];
    const float*    pos_emb       = (const float*)d_in[6];
    const float*    Wq            = (const float*)d_in[7];
    const float*    bq            = (const float*)d_in[8];
    const float*    Wkv           = (const float*)d_in[9];
    const float*    bkv           = (const float*)d_in[10];
    const float*    Wo            = (const float*)d_in[11];
    const float*    bo            = (const float*)d_in[12];
    const float*    Wpos          = (const float*)d_in[13];
    const float*    pbu           = (const float*)d_in[14];
    const float*    pbv           = (const float*)d_in[15];

    float* out      = (float*)d_out;
    float* out_rcu  = out;                                    // (R+U, B, D)
    float* out_mem  = out + (size_t)RUc * Bc * Dc;            // (S, B, D)
    float* out_key  = out + (size_t)Qc * Bc * Dc;             // (KV, B, D)
    float* out_val  = out_key + (size_t)KVc * Bc * Dc;        // (KV, B, D)

    void *p_qin_, *p_query_, *p_pos_, *p_attn_, *p_kvin_;
    cudaGetSymbolAddress(&p_qin_,  g_qin);
    cudaGetSymbolAddress(&p_kvin_, g_kvin);
    cudaGetSymbolAddress(&p_query_, g_query);
    cudaGetSymbolAddress(&p_pos_,  g_pos);
    cudaGetSymbolAddress(&p_attn_, g_attn);
    float* p_qin   = (float*)p_qin_;
    float* p_kvin  = (float*)p_kvin_;
    float* p_query = (float*)p_query_;
    float* p_pos   = (float*)p_pos_;
    float* p_attn  = (float*)p_attn_;

    const int FUSED_SMEM = 70656;
    cudaFuncSetAttribute(fused_attn, cudaFuncAttributeMaxDynamicSharedMemorySize, FUSED_SMEM);

    // 1) gathers
    gather_qin<<<(Qc * Bc * Dc + 255) / 256, 256>>>(right_context, utterance, summary);
    gather_kvin<<<(KVc * Bc * Dc + 255) / 256, 256>>>(memory, right_context, utterance);

    // 2) projections (tf32 MMA)
    proj_mma<<<dim3(Dc / 64, (Qc * Bc) / 128), 256>>>(p_qin, Wq, bq, Qc * Bc, Dc, Dc, p_query, nullptr, 0);
    proj_mma<<<dim3((2 * Dc) / 64, (KVc * Bc) / 128), 256>>>(p_kvin, Wkv, bkv, KVc * Bc, 2 * Dc, Dc, out_key, out_val, 1);
    proj_mma<<<dim3(Dc / 64, (PEc + 127) / 128), 256>>>(pos_emb, Wpos, nullptr, PEc, Dc, Dc, p_pos, nullptr, 0);

    // 3) dense rel-shifted bd scores
    bd_dense<<<dim3(9, Uc / 64, BHc), 128>>>(pbv);

    // 4) fused attention (AC scores + bd + masks + softmax + PV)
    fused_attn<<<dim3((Qc + 63) / 64, BHc), 128, FUSED_SMEM>>>(out_key, out_val, pbu, attn_mask, lengths);

    // 5) output projection with split + clip
    proj_mma<<<dim3(Dc / 64, (Qc * Bc) / 128), 256>>>(p_attn, Wo, bo, Qc * Bc, Dc, Dc, out_rcu, out_mem, 2);
}

// round 8
// speedup vs baseline: 4.5093x; 1.5209x over previous
#include <cuda_runtime.h>
#include <stdint.h>

#define Uc   512
#define Bc   16
#define Dc   512
#define Hc   8
#define Rc   32
#define Sc   16
#define Mc   32
#define HDc  64
#define Qc   560
#define KVc  576
#define PEc  1023
#define BHc  128
#define RUc  544
#define SCALE_F 0.125f
#define NEG_INF_F -100000000.0f

// ---------------- scratch ---------------------------------------------------
__device__ float g_query[Qc * Bc * Dc];
__device__ float g_pos[PEc * Dc];
__device__ float g_bd[(size_t)BHc * Uc * Uc];   // dense rel-shifted bd scores
__device__ float g_attn[Qc * Bc * Dc];

// ---------------- tf32 helpers ---------------------------------------------
__device__ __forceinline__ unsigned f2tf(float x) {
    unsigned r;
    asm("cvt.rna.tf32.f32 %0, %1;" : "=r"(r) : "f"(x));
    return r;
}

__device__ __forceinline__ void mma8(float* c, const unsigned* a, const unsigned* b) {
    asm volatile(
        "mma.sync.aligned.m16n8k8.row.col.f32.tf32.tf32.f32 "
        "{%0,%1,%2,%3},{%4,%5,%6,%7},{%8,%9},{%0,%1,%2,%3};"
        : "+f"(c[0]), "+f"(c[1]), "+f"(c[2]), "+f"(c[3])
        : "r"(a[0]), "r"(a[1]), "r"(a[2]), "r"(a[3]), "r"(b[0]), "r"(b[1]));
}

// ---------------- projection GEMM: C = concat(A0,A1,A2)(M,K) @ W(N,K)^T -----
// A row selection: row<t1 -> A0, row<t2 -> A1[row-t1], else A2[row-t2].
// Software-pipelined: next K-tile prefetched into registers during MMA.
__global__ void __launch_bounds__(256, 2)
proj_mma(const float* __restrict__ A0, const float* __restrict__ A1,
         const float* __restrict__ A2, int t1, int t2,
         const float* __restrict__ W, const float* __restrict__ bias,
         int M, int N, int K,
         float* __restrict__ out1, float* __restrict__ out2, int mode) {
    __shared__ unsigned As[128][36];
    __shared__ unsigned Bs[64][36];
    const int t = threadIdx.x;
    const int warp = t >> 5, lane = t & 31;
    const int g = lane >> 2, tig = lane & 3;
    const int wm = warp & 3, wn = warp >> 2;
    const int rowBase = blockIdx.y * 128, colBase = blockIdx.x * 64;

    const int rs  = t >> 3;            // smem row within group of 32
    const int c4  = (t & 7) << 2;      // k-offset 0..28

    const float* aptr[4];
    bool aval[4];
#pragma unroll
    for (int i = 0; i < 4; i++) {
        int grow = rowBase + rs + 32 * i;
        aval[i] = (grow < M);
        const float* s; int ro;
        if (grow < t1)      { s = A0; ro = grow; }
        else if (grow < t2) { s = A1; ro = grow - t1; }
        else                { s = A2; ro = grow - t2; }
        aptr[i] = s + (size_t)ro * K + c4;
    }
    const float* bptr[2];
#pragma unroll
    for (int i = 0; i < 2; i++)
        bptr[i] = W + (size_t)(colBase + rs + 32 * i) * K + c4;

    float acc[2][4][4];
#pragma unroll
    for (int mi = 0; mi < 2; mi++)
#pragma unroll
        for (int ni = 0; ni < 4; ni++)
#pragma unroll
            for (int j = 0; j < 4; j++) acc[mi][ni][j] = 0.f;

    float4 ar[4], br[2];
#pragma unroll
    for (int i = 0; i < 4; i++)
        ar[i] = aval[i] ? *(const float4*)(aptr[i]) : make_float4(0.f, 0.f, 0.f, 0.f);
#pragma unroll
    for (int i = 0; i < 2; i++)
        br[i] = *(const float4*)(bptr[i]);

    for (int k0 = 0; k0 < K; k0 += 32) {
#pragma unroll
        for (int i = 0; i < 4; i++) {
            int r = rs + 32 * i;
            As[r][c4 + 0] = f2tf(ar[i].x); As[r][c4 + 1] = f2tf(ar[i].y);
            As[r][c4 + 2] = f2tf(ar[i].z); As[r][c4 + 3] = f2tf(ar[i].w);
        }
#pragma unroll
        for (int i = 0; i < 2; i++) {
            int r = rs + 32 * i;
            Bs[r][c4 + 0] = f2tf(br[i].x); Bs[r][c4 + 1] = f2tf(br[i].y);
            Bs[r][c4 + 2] = f2tf(br[i].z); Bs[r][c4 + 3] = f2tf(br[i].w);
        }
        __syncthreads();

        if (k0 + 32 < K) {
#pragma unroll
            for (int i = 0; i < 4; i++)
                ar[i] = aval[i] ? *(const float4*)(aptr[i] + k0 + 32)
                                : make_float4(0.f, 0.f, 0.f, 0.f);
#pragma unroll
            for (int i = 0; i < 2; i++)
                br[i] = *(const float4*)(bptr[i] + k0 + 32);
        }

#pragma unroll
        for (int ks = 0; ks < 4; ks++) {
            unsigned af[2][4], bf[4][2];
#pragma unroll
            for (int mi = 0; mi < 2; mi++) {
                int r0 = wm * 32 + mi * 16 + g;
                int c0 = ks * 8 + tig;
                af[mi][0] = As[r0][c0];
                af[mi][1] = As[r0 + 8][c0];
                af[mi][2] = As[r0][c0 + 4];
                af[mi][3] = As[r0 + 8][c0 + 4];
            }
#pragma unroll
            for (int ni = 0; ni < 4; ni++) {
                int n0 = wn * 32 + ni * 8 + g;
                int kk = ks * 8 + tig;
                bf[ni][0] = Bs[n0][kk];
                bf[ni][1] = Bs[n0][kk + 4];
            }
#pragma unroll
            for (int mi = 0; mi < 2; mi++)
#pragma unroll
                for (int ni = 0; ni < 4; ni++)
                    mma8(acc[mi][ni], af[mi], bf[ni]);
        }
        __syncthreads();
    }

#pragma unroll
    for (int mi = 0; mi < 2; mi++) {
#pragma unroll
        for (int ni = 0; ni < 4; ni++) {
            int col = colBase + wn * 32 + ni * 8 + 2 * tig;
            float b0 = bias ? bias[col] : 0.f;
            float b1 = bias ? bias[col + 1] : 0.f;
#pragma unroll
            for (int half = 0; half < 2; half++) {
                int row = rowBase + wm * 32 + mi * 16 + g + half * 8;
                if (row >= M) continue;
                float v0 = acc[mi][ni][half * 2 + 0] + b0;
                float v1 = acc[mi][ni][half * 2 + 1] + b1;
                if (mode == 0) {
                    out1[(size_t)row * N + col]     = v0;
                    out1[(size_t)row * N + col + 1] = v1;
                } else if (mode == 1) {
                    if (col < Dc) {
                        out1[(size_t)row * Dc + col]     = v0;
                        out1[(size_t)row * Dc + col + 1] = v1;
                    } else {
                        out2[(size_t)row * Dc + col - Dc]     = v0;
                        out2[(size_t)row * Dc + col - Dc + 1] = v1;
                    }
                } else {
                    int q = row >> 4;
                    if (q < RUc) {
                        out1[(size_t)row * Dc + col]     = v0;
                        out1[(size_t)row * Dc + col + 1] = v1;
                    } else {
                        v0 = fminf(10.0f, fmaxf(-10.0f, v0));
                        v1 = fminf(10.0f, fmaxf(-10.0f, v1));
                        out2[(size_t)(row - RUc * Bc) * Dc + col]     = v0;
                        out2[(size_t)(row - RUc * Bc) * Dc + col + 1] = v1;
                    }
                }
            }
        }
    }
}

// ---------------- BD dense: g_bd[n][u][jj] = dot(qv_u, pos_{jj+511-u}) ------
__global__ void __launch_bounds__(128, 4)
bd_dense(const float* __restrict__ pbv) {
    __shared__ unsigned As[64][36];
    __shared__ unsigned Bs[64][36];
    const int t = threadIdx.x;
    const int warp = t >> 5, lane = t & 31;
    const int g = lane >> 2, tig = lane & 3;
    const int wm = warp & 1, wn = warp >> 1;
    const int n = blockIdx.z, b = n >> 3, h = n & 7;
    const int rowBase = blockIdx.y * 64;                      // u0
    const int colBase = 448 - rowBase + blockIdx.x * 64;      // p0 (>= 0)

    float acc[2][4][4];
#pragma unroll
    for (int mi = 0; mi < 2; mi++)
#pragma unroll
        for (int ni = 0; ni < 4; ni++)
#pragma unroll
            for (int j = 0; j < 4; j++) acc[mi][ni][j] = 0.f;

    for (int k0 = 0; k0 < HDc; k0 += 32) {
#pragma unroll
        for (int i = 0; i < 4; i++) {
            int idx = t + i * 128;
            int r = idx >> 3, c4 = (idx & 7) << 2;
            int u = rowBase + r;
            float4 v = *(const float4*)(g_query + ((size_t)(Rc + u) * Bc + b) * Dc + h * HDc + k0 + c4);
            float4 p = *(const float4*)(pbv + h * HDc + k0 + c4);
            v.x += p.x; v.y += p.y; v.z += p.z; v.w += p.w;
            As[r][c4 + 0] = f2tf(v.x); As[r][c4 + 1] = f2tf(v.y);
            As[r][c4 + 2] = f2tf(v.z); As[r][c4 + 3] = f2tf(v.w);
        }
#pragma unroll
        for (int i = 0; i < 4; i++) {
            int idx = t + i * 128;
            int r = idx >> 3, c4 = (idx & 7) << 2;
            int p = colBase + r;
            float4 v = make_float4(0.f, 0.f, 0.f, 0.f);
            if (p < PEc)
                v = *(const float4*)(g_pos + (size_t)p * Dc + h * HDc + k0 + c4);
            Bs[r][c4 + 0] = f2tf(v.x); Bs[r][c4 + 1] = f2tf(v.y);
            Bs[r][c4 + 2] = f2tf(v.z); Bs[r][c4 + 3] = f2tf(v.w);
        }
        __syncthreads();

#pragma unroll
        for (int ks = 0; ks < 4; ks++) {
            unsigned af[2][4], bf[4][2];
#pragma unroll
            for (int mi = 0; mi < 2; mi++) {
                int r0 = wm * 32 + mi * 16 + g;
                int c0 = ks * 8 + tig;
                af[mi][0] = As[r0][c0];     af[mi][1] = As[r0 + 8][c0];
                af[mi][2] = As[r0][c0 + 4]; af[mi][3] = As[r0 + 8][c0 + 4];
            }
#pragma unroll
            for (int ni = 0; ni < 4; ni++) {
                int n0 = wn * 32 + ni * 8 + g;
                int kk = ks * 8 + tig;
                bf[ni][0] = Bs[n0][kk];
                bf[ni][1] = Bs[n0][kk + 4];
            }
#pragma unroll
            for (int mi = 0; mi < 2; mi++)
#pragma unroll
                for (int ni = 0; ni < 4; ni++)
                    mma8(acc[mi][ni], af[mi], bf[ni]);
        }
        __syncthreads();
    }

#pragma unroll
    for (int mi = 0; mi < 2; mi++) {
#pragma unroll
        for (int half = 0; half < 2; half++) {
            int u = rowBase + wm * 32 + mi * 16 + g + half * 8;
#pragma unroll
            for (int ni = 0; ni < 4; ni++) {
#pragma unroll
                for (int jc = 0; jc < 2; jc++) {
                    int p = colBase + wn * 32 + ni * 8 + 2 * tig + jc;
                    if (p >= PEc) continue;
                    int jj = p + u - (Uc - 1);
                    if (jj >= 0 && jj < Uc)
                        g_bd[((size_t)n * Uc + u) * Uc + jj] = acc[mi][ni][half * 2 + jc];
                }
            }
        }
    }
}

// ---------------- fused attention: S = QK^T + bd, softmax, O = P V ----------
// One block per (n, 64-row q-tile). 128 threads, 4 warps (2 q x 2 k/d).
// Mask + bd staged coalesced into the P smem region each KV tile.
// P/Ms stride = 68 floats (row offset 272B: 16B-aligned for float4 staging).
__global__ void __launch_bounds__(128)
fused_attn(const float* __restrict__ keyt,
           const float* __restrict__ valt,
           const float* __restrict__ pbu,
           const unsigned* __restrict__ mask,
           const int* __restrict__ lengths) {
    extern __shared__ unsigned char dynsmem[];
    unsigned (*Qs)[68] = (unsigned (*)[68])(dynsmem);             // 17408B
    unsigned (*Ks)[68] = (unsigned (*)[68])(dynsmem + 17408);     // 17408B
    unsigned (*Vs)[72] = (unsigned (*)[72])(dynsmem + 34816);     // 18432B
    unsigned (*Ps)[68] = (unsigned (*)[68])(dynsmem + 53248);     // 17408B
    float    (*Ms)[68] = (float    (*)[68])(dynsmem + 53248);     // same region
    __shared__ float redm[2][64];
    __shared__ float reds[2][64];

    const int t = threadIdx.x;
    const int warp = t >> 5, lane = t & 31;
    const int g = lane >> 2, tig = lane & 3;
    const int wm = warp & 1, wn = warp >> 1;
    const int qBase = blockIdx.x * 64;
    const int n = blockIdx.y, b = n >> 3, h = n & 7;
    const int cutoff = (Mc + Rc) + lengths[b];

    // load Q tile (+pbu) once
#pragma unroll
    for (int i = 0; i < 8; i++) {
        int idx = t + i * 128;
        int r = idx >> 4, c4 = (idx & 15) << 2;
        int q = qBase + r;
        float4 v = make_float4(0.f, 0.f, 0.f, 0.f);
        if (q < Qc) {
            v = *(const float4*)(g_query + ((size_t)q * Bc + b) * Dc + h * HDc + c4);
            float4 p = *(const float4*)(pbu + h * HDc + c4);
            v.x += p.x; v.y += p.y; v.z += p.z; v.w += p.w;
        }
        Qs[r][c4 + 0] = f2tf(v.x); Qs[r][c4 + 1] = f2tf(v.y);
        Qs[r][c4 + 2] = f2tf(v.z); Qs[r][c4 + 3] = f2tf(v.w);
    }

    float o[2][4][4];
#pragma unroll
    for (int mi = 0; mi < 2; mi++)
#pragma unroll
        for (int ni = 0; ni < 4; ni++)
#pragma unroll
            for (int j = 0; j < 4; j++) o[mi][ni][j] = 0.f;
    float mrun[2][2], lrun[2][2];
#pragma unroll
    for (int mi = 0; mi < 2; mi++)
#pragma unroll
        for (int hf = 0; hf < 2; hf++) { mrun[mi][hf] = -3.0e38f; lrun[mi][hf] = 0.f; }

    for (int kt = 0; kt < KVc / 64; kt++) {
        const int k0 = kt * 64;
        const bool hasbd = (kt >= 1);
        __syncthreads();   // previous iteration's MMA reads of Ks/Vs/Ps done

        // load K, V tiles (coalesced) and stage mask/bd into Ms
#pragma unroll
        for (int i = 0; i < 8; i++) {
            int idx = t + i * 128;
            int r = idx >> 4, c4 = (idx & 15) << 2;
            size_t goff = ((size_t)(k0 + r) * Bc + b) * Dc + h * HDc + c4;
            float4 kv = *(const float4*)(keyt + goff);
            Ks[r][c4 + 0] = f2tf(kv.x); Ks[r][c4 + 1] = f2tf(kv.y);
            Ks[r][c4 + 2] = f2tf(kv.z); Ks[r][c4 + 3] = f2tf(kv.w);
            float4 vv = *(const float4*)(valt + goff);
            Vs[r][c4 + 0] = f2tf(vv.x); Vs[r][c4 + 1] = f2tf(vv.y);
            Vs[r][c4 + 2] = f2tf(vv.z); Vs[r][c4 + 3] = f2tf(vv.w);

            // stage: Ms = masked ? -1e30 : bd
            int q = qBase + r;
            int k = k0 + c4;
            float4 st;
            if (q < Qc) {
                uint4 mk = *(const uint4*)(mask + (size_t)q * KVc + k);
                float4 bd4 = make_float4(0.f, 0.f, 0.f, 0.f);
                if (hasbd && q >= Rc && q < Rc + Uc)
                    bd4 = *(const float4*)(g_bd + ((size_t)n * Uc + (q - Rc)) * Uc + (k - (Mc + Rc)));
                st.x = (mk.x != 0u || k + 0 >= cutoff) ? -1e30f : bd4.x;
                st.y = (mk.y != 0u || k + 1 >= cutoff) ? -1e30f : bd4.y;
                st.z = (mk.z != 0u || k + 2 >= cutoff) ? -1e30f : bd4.z;
                st.w = (mk.w != 0u || k + 3 >= cutoff) ? -1e30f : bd4.w;
            } else {
                st = make_float4(-1e30f, -1e30f, -1e30f, -1e30f);
            }
            *(float4*)&Ms[r][c4] = st;
        }
        __syncthreads();

        // S = Q K^T (64q x 64k, K over d=64)
        float s[2][4][4];
#pragma unroll
        for (int mi = 0; mi < 2; mi++)
#pragma unroll
            for (int ni = 0; ni < 4; ni++)
#pragma unroll
                for (int j = 0; j < 4; j++) s[mi][ni][j] = 0.f;
#pragma unroll
        for (int ks = 0; ks < 8; ks++) {
            unsigned af[2][4], bf[4][2];
#pragma unroll
            for (int mi = 0; mi < 2; mi++) {
                int r0 = wm * 32 + mi * 16 + g;
                int c0 = ks * 8 + tig;
                af[mi][0] = Qs[r0][c0];     af[mi][1] = Qs[r0 + 8][c0];
                af[mi][2] = Qs[r0][c0 + 4]; af[mi][3] = Qs[r0 + 8][c0 + 4];
            }
#pragma unroll
            for (int ni = 0; ni < 4; ni++) {
                int n0 = wn * 32 + ni * 8 + g;
                int kk = ks * 8 + tig;
                bf[ni][0] = Ks[n0][kk];
                bf[ni][1] = Ks[n0][kk + 4];
            }
#pragma unroll
            for (int mi = 0; mi < 2; mi++)
#pragma unroll
                for (int ni = 0; ni < 4; ni++)
                    mma8(s[mi][ni], af[mi], bf[ni]);
        }

        // epilogue: v = fmax((s + Ms) * SCALE, NEG_INF)
#pragma unroll
        for (int mi = 0; mi < 2; mi++)
#pragma unroll
            for (int j = 0; j < 4; j++) {
                int row = wm * 32 + mi * 16 + (j >> 1) * 8 + g;
#pragma unroll
                for (int ni = 0; ni < 4; ni++) {
                    int col = wn * 32 + ni * 8 + 2 * tig + (j & 1);
                    float v = (s[mi][ni][j] + Ms[row][col]) * SCALE_F;
                    s[mi][ni][j] = fmaxf(v, NEG_INF_F);
                }
            }

        // row max (tig shuffle -> cross-warp via smem)
#pragma unroll
        for (int mi = 0; mi < 2; mi++)
#pragma unroll
            for (int hf = 0; hf < 2; hf++) {
                float x = -3.4e38f;
#pragma unroll
                for (int ni = 0; ni < 4; ni++)
                    x = fmaxf(x, fmaxf(s[mi][ni][2 * hf], s[mi][ni][2 * hf + 1]));
                x = fmaxf(x, __shfl_xor_sync(0xffffffffu, x, 1));
                x = fmaxf(x, __shfl_xor_sync(0xffffffffu, x, 2));
                if (tig == 0) redm[wn][wm * 32 + mi * 16 + hf * 8 + g] = x;
            }
        __syncthreads();

        float mnew[2][2], fac[2][2];
#pragma unroll
        for (int mi = 0; mi < 2; mi++)
#pragma unroll
            for (int hf = 0; hf < 2; hf++) {
                int row = wm * 32 + mi * 16 + hf * 8 + g;
                float mt = fmaxf(redm[0][row], redm[1][row]);
                float mn = fmaxf(mrun[mi][hf], mt);
                fac[mi][hf] = __expf(mrun[mi][hf] - mn);
                mnew[mi][hf] = mn;
            }

        // exp + per-warp row sums
#pragma unroll
        for (int mi = 0; mi < 2; mi++)
#pragma unroll
            for (int hf = 0; hf < 2; hf++) {
                float ssum = 0.f;
#pragma unroll
                for (int ni = 0; ni < 4; ni++) {
#pragma unroll
                    for (int c = 0; c < 2; c++) {
                        float p = __expf(s[mi][ni][2 * hf + c] - mnew[mi][hf]);
                        s[mi][ni][2 * hf + c] = p;
                        ssum += p;
                    }
                }
                ssum += __shfl_xor_sync(0xffffffffu, ssum, 1);
                ssum += __shfl_xor_sync(0xffffffffu, ssum, 2);
                if (tig == 0) reds[wn][wm * 32 + mi * 16 + hf * 8 + g] = ssum;
            }

        // rescale O accumulators
#pragma unroll
        for (int mi = 0; mi < 2; mi++)
#pragma unroll
            for (int ni = 0; ni < 4; ni++)
#pragma unroll
                for (int j = 0; j < 4; j++)
                    o[mi][ni][j] *= fac[mi][j >> 1];

        // write P tile to smem (tf32) — same element ownership as Ms reads
#pragma unroll
        for (int mi = 0; mi < 2; mi++)
#pragma unroll
            for (int j = 0; j < 4; j++) {
                int row = wm * 32 + mi * 16 + (j >> 1) * 8 + g;
#pragma unroll
                for (int ni = 0; ni < 4; ni++) {
                    int col = wn * 32 + ni * 8 + 2 * tig + (j & 1);
                    Ps[row][col] = f2tf(s[mi][ni][j]);
                }
            }
        __syncthreads();

        // update l, m
#pragma unroll
        for (int mi = 0; mi < 2; mi++)
#pragma unroll
            for (int hf = 0; hf < 2; hf++) {
                int row = wm * 32 + mi * 16 + hf * 8 + g;
                lrun[mi][hf] = lrun[mi][hf] * fac[mi][hf] + reds[0][row] + reds[1][row];
                mrun[mi][hf] = mnew[mi][hf];
            }

        // O += P V  (64q x 64d, K over k=64)
#pragma unroll
        for (int ks = 0; ks < 8; ks++) {
            unsigned af[2][4], bf[4][2];
#pragma unroll
            for (int mi = 0; mi < 2; mi++) {
                int r0 = wm * 32 + mi * 16 + g;
                int c0 = ks * 8 + tig;
                af[mi][0] = Ps[r0][c0];     af[mi][1] = Ps[r0 + 8][c0];
                af[mi][2] = Ps[r0][c0 + 4]; af[mi][3] = Ps[r0 + 8][c0 + 4];
            }
#pragma unroll
            for (int ni = 0; ni < 4; ni++) {
                int col = wn * 32 + ni * 8 + g;
                int kk = ks * 8 + tig;
                bf[ni][0] = Vs[kk][col];
                bf[ni][1] = Vs[kk + 4][col];
            }
#pragma unroll
            for (int mi = 0; mi < 2; mi++)
#pragma unroll
                for (int ni = 0; ni < 4; ni++)
                    mma8(o[mi][ni], af[mi], bf[ni]);
        }
    }

    // final: O / l -> g_attn
#pragma unroll
    for (int mi = 0; mi < 2; mi++)
#pragma unroll
        for (int j = 0; j < 4; j++) {
            int row = wm * 32 + mi * 16 + (j >> 1) * 8 + g;
            int q = qBase + row;
            if (q >= Qc) continue;
            float inv = 1.0f / lrun[mi][j >> 1];
#pragma unroll
            for (int ni = 0; ni < 4; ni++) {
                int d = wn * 32 + ni * 8 + 2 * tig + (j & 1);
                g_attn[((size_t)q * Bc + b) * Dc + h * HDc + d] = o[mi][ni][j] * inv;
            }
        }
}

// ---------------- launch ----------------------------------------------------
extern "C" void kernel_launch(void* const* d_in, const int* in_sizes, int n_in,
                              void* d_out, int out_size) {
    const float*    utterance     = (const float*)d_in[0];
    const int*      lengths       = (const int*)d_in[1];
    const float*    right_context = (const float*)d_in[2];
    const float*    summary       = (const float*)d_in[3];
    const float*    memory        = (const float*)d_in[4];
    const unsigned* attn_mask     = (const unsigned*)d_in[5];
    const float*    pos_emb       = (const float*)d_in[6];
    const float*    Wq            = (const float*)d_in[7];
    const float*    bq            = (const float*)d_in[8];
    const float*    Wkv           = (const float*)d_in[9];
    const float*    bkv           = (const float*)d_in[10];
    const float*    Wo            = (const float*)d_in[11];
    const float*    bo            = (const float*)d_in[12];
    const float*    Wpos          = (const float*)d_in[13];
    const float*    pbu           = (const float*)d_in[14];
    const float*    pbv           = (const float*)d_in[15];

    float* out      = (float*)d_out;
    float* out_rcu  = out;                                    // (R+U, B, D)
    float* out_mem  = out + (size_t)RUc * Bc * Dc;            // (S, B, D)
    float* out_key  = out + (size_t)Qc * Bc * Dc;             // (KV, B, D)
    float* out_val  = out_key + (size_t)KVc * Bc * Dc;        // (KV, B, D)

    void *p_query_, *p_pos_, *p_attn_;
    cudaGetSymbolAddress(&p_query_, g_query);
    cudaGetSymbolAddress(&p_pos_,  g_pos);
    cudaGetSymbolAddress(&p_attn_, g_attn);
    float* p_query = (float*)p_query_;
    float* p_pos   = (float*)p_pos_;
    float* p_attn  = (float*)p_attn_;

    const int FUSED_SMEM = 70656;
    cudaFuncSetAttribute(fused_attn, cudaFuncAttributeMaxDynamicSharedMemorySize, FUSED_SMEM);

    // 1) projections (tf32 MMA) with fused concat-gather on A
    proj_mma<<<dim3(Dc / 64, (Qc * Bc) / 128), 256>>>(
        right_context, utterance, summary, Rc * Bc, RUc * Bc,
        Wq, bq, Qc * Bc, Dc, Dc, p_query, nullptr, 0);
    proj_mma<<<dim3((2 * Dc) / 64, (KVc * Bc) / 128), 256>>>(
        memory, right_context, utterance, Mc * Bc, (Mc + Rc) * Bc,
        Wkv, bkv, KVc * Bc, 2 * Dc, Dc, out_key, out_val, 1);
    proj_mma<<<dim3(Dc / 64, (PEc + 127) / 128), 256>>>(
        pos_emb, pos_emb, pos_emb, PEc, PEc,
        Wpos, nullptr, PEc, Dc, Dc, p_pos, nullptr, 0);

    // 2) dense rel-shifted bd scores
    bd_dense<<<dim3(9, Uc / 64, BHc), 128>>>(pbv);

    // 3) fused attention (AC scores + bd + masks + softmax + PV)
    fused_attn<<<dim3((Qc + 63) / 64, BHc), 128, FUSED_SMEM>>>(out_key, out_val, pbu, attn_mask, lengths);

    // 4) output projection with split + clip
    proj_mma<<<dim3(Dc / 64, (Qc * Bc) / 128), 256>>>(
        p_attn, p_attn, p_attn, Qc * Bc, Qc * Bc,
        Wo, bo, Qc * Bc, Dc, Dc, out_rcu, out_mem, 2);
}